// round 15
// baseline (speedup 1.0000x reference)
#include <cuda_runtime.h>
#include <cuda_fp16.h>
#include <math.h>

#define Bt 8192
#define Dd 1024
#define Hh 4096
#define Ee 4

// output layout: y | probs | top_idx | top_w | aux
#define OFF_PROBS ((size_t)Bt * Dd)
#define OFF_IDX   (OFF_PROBS + (size_t)Bt * Ee)
#define OFF_TOPW  (OFF_IDX + (size_t)Bt * 2)
#define OFF_AUX   (OFF_TOPW + (size_t)Bt * 2)

// ---- static scratch (no allocations allowed) ----
static __device__ int      g_count[Ee];
static __device__ float    g_psum[Ee];
static __device__ int      g_tok[Ee * Bt];
static __device__ float    g_wgt[Ee * Bt];
static __device__ unsigned g_xa_h[(size_t)Ee * Bt * (Dd / 2)];
static __device__ unsigned g_h_h[(size_t)Ee * Bt * (Hh / 2)];
static __device__ unsigned g_w1_h[(size_t)Ee * Hh * (Dd / 2)];
static __device__ unsigned g_w2_h[(size_t)Ee * Dd * (Hh / 2)];

// pack two floats as fp16x2 (f0 low)
__device__ __forceinline__ unsigned packhi(float f0, float f1) {
    unsigned h;
    asm("cvt.rn.f16x2.f32 %0, %1, %2;" : "=r"(h) : "f"(f1), "f"(f0));
    return h;
}

__device__ __forceinline__ void mma_f16(float* c, const unsigned* a, const unsigned* b) {
    asm volatile(
        "mma.sync.aligned.m16n8k16.row.col.f32.f16.f16.f32 "
        "{%0,%1,%2,%3}, {%4,%5,%6,%7}, {%8,%9}, {%0,%1,%2,%3};"
        : "+f"(c[0]), "+f"(c[1]), "+f"(c[2]), "+f"(c[3])
        : "r"(a[0]), "r"(a[1]), "r"(a[2]), "r"(a[3]), "r"(b[0]), "r"(b[1]));
}

__device__ __forceinline__ void ldsm_x4(unsigned &r0, unsigned &r1, unsigned &r2,
                                        unsigned &r3, unsigned addr) {
    asm volatile("ldmatrix.sync.aligned.m8n8.x4.shared.b16 {%0,%1,%2,%3}, [%4];"
                 : "=r"(r0), "=r"(r1), "=r"(r2), "=r"(r3) : "r"(addr));
}

__device__ __forceinline__ void cpa16(unsigned dst, const unsigned* src, int predBytes) {
    asm volatile("cp.async.cg.shared.global [%0], [%1], 16, %2;\n"
                 :: "r"(dst), "l"(src), "r"(predBytes) : "memory");
}

__device__ __forceinline__ float gelu_f(float v) {
    return 0.5f * v * (1.f + erff(v * 0.70710678118654752f));
}

__global__ void k_init() {
    int t = threadIdx.x;
    if (t < Ee) { g_count[t] = 0; g_psum[t] = 0.f; }
}

// transpose + pack (hi only): w [e][R][C] -> oh [e][C][R/2] (fp16x2 packed along R)
__device__ __forceinline__ void tr_body(
    const float* __restrict__ w, unsigned* __restrict__ oh, int R, int C)
{
    __shared__ float s[32][33];
    int e = blockIdx.z;
    const float* wp = w + (size_t)e * R * C;
    unsigned* ohp = oh + (size_t)e * C * (R / 2);
    int r0 = blockIdx.y * 32, c0 = blockIdx.x * 32;
    int tx = threadIdx.x & 31, ty = threadIdx.x >> 5;  // (32, 8)
    #pragma unroll
    for (int j = 0; j < 4; j++)
        s[ty + 8 * j][tx] = wp[(size_t)(r0 + ty + 8 * j) * C + c0 + tx];
    __syncthreads();
    int idx = threadIdx.x;
    int cc = idx >> 4;          // 0..15
    int rq = idx & 15;          // 0..15
    #pragma unroll
    for (int j = 0; j < 2; j++) {
        int c = cc + 16 * j;
        size_t o = (size_t)(c0 + c) * (R / 2) + (r0 >> 1) + rq;
        ohp[o] = packhi(s[2 * rq][c], s[2 * rq + 1][c]);
    }
}

__global__ __launch_bounds__(256) void k_tr_w1(const float* __restrict__ w) {
    tr_body(w, g_w1_h, Dd, Hh);
}
__global__ __launch_bounds__(256) void k_tr_w2(const float* __restrict__ w) {
    tr_body(w, g_w2_h, Hh, Dd);
}

// One block per token: LN stats, gating, softmax, top-2, outputs, packed scatter.
__global__ __launch_bounds__(256) void k_gate(
    const float* __restrict__ x, const float* __restrict__ gw,
    const float* __restrict__ gb, const float* __restrict__ lnw,
    const float* __restrict__ lnb, float* __restrict__ out)
{
    __shared__ float sx[Dd];
    __shared__ float sred[8 * 6];
    __shared__ float sfin[6];
    __shared__ float s_mu, s_rs;
    __shared__ int s_e0, s_e1, s_p0, s_p1;

    int b = blockIdx.x;
    int t = threadIdx.x;
    int lane = t & 31, wid = t >> 5;
    const float* xr = x + (size_t)b * Dd;

    #pragma unroll
    for (int d = t; d < Dd; d += 256) sx[d] = xr[d];
    __syncthreads();

    float v6[6] = {0.f, 0.f, 0.f, 0.f, 0.f, 0.f};
    #pragma unroll
    for (int d = t; d < Dd; d += 256) {
        float v = sx[d];
        v6[0] += v; v6[1] += v * v;
        v6[2] += v * gw[d];
        v6[3] += v * gw[Dd + d];
        v6[4] += v * gw[2 * Dd + d];
        v6[5] += v * gw[3 * Dd + d];
    }
    #pragma unroll
    for (int j = 0; j < 6; j++) {
        #pragma unroll
        for (int o = 16; o > 0; o >>= 1)
            v6[j] += __shfl_down_sync(0xffffffffu, v6[j], o);
    }
    if (lane == 0) {
        #pragma unroll
        for (int j = 0; j < 6; j++) sred[wid * 6 + j] = v6[j];
    }
    __syncthreads();
    if (t < 6) {
        float a = 0.f;
        #pragma unroll
        for (int w8 = 0; w8 < 8; w8++) a += sred[w8 * 6 + t];
        sfin[t] = a;
    }
    __syncthreads();

    if (t == 0) {
        float tot = sfin[0], tot2 = sfin[1];
        float lg[Ee] = { sfin[2] + gb[0], sfin[3] + gb[1],
                         sfin[4] + gb[2], sfin[5] + gb[3] };
        float mu = tot * (1.f / Dd);
        float var = tot2 * (1.f / Dd) - mu * mu;
        s_mu = mu;
        s_rs = rsqrtf(var + 1e-5f);

        float mx = lg[0];
        #pragma unroll
        for (int e = 1; e < Ee; e++) mx = fmaxf(mx, lg[e]);
        float pe[Ee], se = 0.f;
        #pragma unroll
        for (int e = 0; e < Ee; e++) { pe[e] = expf(lg[e] - mx); se += pe[e]; }
        float inv = 1.f / se;
        #pragma unroll
        for (int e = 0; e < Ee; e++) {
            pe[e] *= inv;
            out[OFF_PROBS + (size_t)b * Ee + e] = pe[e];
            atomicAdd(&g_psum[e], pe[e]);
        }
        int i0 = 0;
        #pragma unroll
        for (int e = 1; e < Ee; e++) if (pe[e] > pe[i0]) i0 = e;
        int i1 = (i0 == 0) ? 1 : 0;
        #pragma unroll
        for (int e = 0; e < Ee; e++) if (e != i0 && pe[e] > pe[i1]) i1 = e;

        float w0 = pe[i0], w1 = pe[i1];
        float sw = w0 + w1 + 1e-9f;
        w0 /= sw; w1 /= sw;

        out[OFF_IDX  + (size_t)b * 2 + 0] = (float)i0;
        out[OFF_IDX  + (size_t)b * 2 + 1] = (float)i1;
        out[OFF_TOPW + (size_t)b * 2 + 0] = w0;
        out[OFF_TOPW + (size_t)b * 2 + 1] = w1;

        int q0 = atomicAdd(&g_count[i0], 1);
        g_wgt[i0 * Bt + q0] = w0; g_tok[i0 * Bt + q0] = b;
        int q1 = atomicAdd(&g_count[i1], 1);
        g_wgt[i1 * Bt + q1] = w1; g_tok[i1 * Bt + q1] = b;
        s_e0 = i0; s_e1 = i1; s_p0 = q0; s_p1 = q1;
    }
    __syncthreads();

    float mu = s_mu, rs = s_rs;
    int e0 = s_e0, e1 = s_e1;
    unsigned* h0 = g_xa_h + ((size_t)e0 * Bt + s_p0) * (Dd / 2);
    unsigned* h1 = g_xa_h + ((size_t)e1 * Bt + s_p1) * (Dd / 2);
    const float* lw0 = lnw + (size_t)e0 * Dd; const float* lb0 = lnb + (size_t)e0 * Dd;
    const float* lw1 = lnw + (size_t)e1 * Dd; const float* lb1 = lnb + (size_t)e1 * Dd;
    for (int dq = t; dq < Dd / 2; dq += 256) {
        int d = dq * 2;
        float xn0 = (sx[d] - mu) * rs;
        float xn1 = (sx[d + 1] - mu) * rs;
        h0[dq] = packhi(xn0 * lw0[d] + lb0[d], xn1 * lw0[d + 1] + lb0[d + 1]);
        h1[dq] = packhi(xn0 * lw1[d] + lb1[d], xn1 * lw1[d + 1] + lb1[d + 1]);
    }
}

// smem layout: [stage 0..4][arr A,B][row 0..127][kq 0..19(pad)]
// 80B row stride (20 words): 20i mod 32 = {0,20,8,28,16,4,24,12} -> conflict-free.
#define SOFF(s, a, r, k) ((((s) * 2 + (a)) * 128 + (r)) * 20 + (k))
#define NSTG 5
#define SMEM_BYTES (NSTG * 2 * 128 * 20 * 4)   // 102400

// single-pass fp16 mainloop (fp32 accum): block tile 128x128, 8 warps (4m x 2n),
// warp tile 32x64. 5-stage cp.async, k32 per stage, one __syncthreads per k32.
__device__ __forceinline__ void run_mainloop(
    unsigned sbase,
    const unsigned* __restrict__ Ahp, const unsigned* __restrict__ Bhp,
    int Mrem, int Kp, int iters, int t, float acc[2][8][4])
{
    const int lane = t & 31, w = t >> 5;
    const int wm = (w >> 1) * 32, wn = (w & 1) * 64;
    const int lm = t >> 1, lc = t & 1;
    const int predA = (lm < Mrem) ? 16 : 0;
    const size_t gOfs = (size_t)lm * Kp + lc * 8;

    const int aRow = wm + (lane & 7) + ((lane >> 3) & 1) * 8;
    const int aChk = ((lane >> 4) & 1) * 4;
    const int bRow = wn + (lane & 7) + (lane >> 4) * 8;
    const int bChk = ((lane >> 3) & 1) * 4;

    // prologue: stages 0..3
    #pragma unroll
    for (int p = 0; p < NSTG - 1; p++) {
        size_t ko = gOfs + (size_t)p * 16;
        cpa16(sbase + SOFF(p, 0, lm, lc * 8) * 4,     Ahp + ko,     predA);
        cpa16(sbase + SOFF(p, 0, lm, lc * 8 + 4) * 4, Ahp + ko + 4, predA);
        cpa16(sbase + SOFF(p, 1, lm, lc * 8) * 4,     Bhp + ko,     16);
        cpa16(sbase + SOFF(p, 1, lm, lc * 8 + 4) * 4, Bhp + ko + 4, 16);
        asm volatile("cp.async.commit_group;\n" ::: "memory");
    }

    int s = 0, sp = NSTG - 1;
    for (int it = 0; it < iters; ++it) {
        int rem = iters - it - 1;   // stages committed beyond current
        if (rem >= 3)
            asm volatile("cp.async.wait_group 3;\n" ::: "memory");
        else if (rem == 2)
            asm volatile("cp.async.wait_group 2;\n" ::: "memory");
        else if (rem == 1)
            asm volatile("cp.async.wait_group 1;\n" ::: "memory");
        else
            asm volatile("cp.async.wait_group 0;\n" ::: "memory");
        __syncthreads();

        if (it + NSTG - 1 < iters) {
            size_t ko = gOfs + (size_t)(it + NSTG - 1) * 16;
            cpa16(sbase + SOFF(sp, 0, lm, lc * 8) * 4,     Ahp + ko,     predA);
            cpa16(sbase + SOFF(sp, 0, lm, lc * 8 + 4) * 4, Ahp + ko + 4, predA);
            cpa16(sbase + SOFF(sp, 1, lm, lc * 8) * 4,     Bhp + ko,     16);
            cpa16(sbase + SOFF(sp, 1, lm, lc * 8 + 4) * 4, Bhp + ko + 4, 16);
            asm volatile("cp.async.commit_group;\n" ::: "memory");
        }

        #pragma unroll
        for (int kk = 0; kk < 2; kk++) {
            unsigned ah[2][4], bh[8][2];
            #pragma unroll
            for (int mt = 0; mt < 2; mt++) {
                ldsm_x4(ah[mt][0], ah[mt][1], ah[mt][2], ah[mt][3],
                        sbase + SOFF(s, 0, aRow + 16 * mt, aChk + 8 * kk) * 4);
            }
            #pragma unroll
            for (int ntp = 0; ntp < 4; ntp++) {
                ldsm_x4(bh[2 * ntp][0], bh[2 * ntp][1],
                        bh[2 * ntp + 1][0], bh[2 * ntp + 1][1],
                        sbase + SOFF(s, 1, bRow + 16 * ntp, bChk + 8 * kk) * 4);
            }
            #pragma unroll
            for (int nt = 0; nt < 8; nt++) {
                #pragma unroll
                for (int mt = 0; mt < 2; mt++) {
                    mma_f16(acc[mt][nt], ah[mt], bh[nt]);
                }
            }
        }
        s  = (s  == NSTG - 1) ? 0 : s + 1;
        sp = (sp == NSTG - 1) ? 0 : sp + 1;
    }
}

// GEMM1 (single expert e): H_e = GELU(Xa_e @ W1[e]^T + b1[e]); packed fp16 out.
// do_aux!=0: block (0,0) thread 0 writes the aux-loss scalar.
__global__ __launch_bounds__(256, 2) void k_gemm1(const float* __restrict__ b1,
                                                  float* __restrict__ out,
                                                  int e, int do_aux) {
    int M = g_count[e];
    int m0 = blockIdx.y * 128;

    if (do_aux && blockIdx.x == 0 && blockIdx.y == 0 && threadIdx.x == 0) {
        float a = 0.f;
        #pragma unroll
        for (int ee = 0; ee < Ee; ee++)
            a += ((float)g_count[ee] * (1.f / (Bt * 2))) * (g_psum[ee] * (1.f / Bt));
        out[OFF_AUX] = (float)Ee * a;
    }

    if (m0 >= M) return;
    int n0 = blockIdx.x * 128;

    extern __shared__ unsigned sm[];
    unsigned sbase;
    asm("{ .reg .u64 tt; cvta.to.shared.u64 tt, %1; cvt.u32.u64 %0, tt; }"
        : "=r"(sbase) : "l"(sm));

    const int Kp = Dd / 2;
    const unsigned* Ahp = g_xa_h + ((size_t)e * Bt + m0) * Kp;
    const unsigned* Bhp = g_w1_h + (size_t)e * Hh * Kp + (size_t)n0 * Kp;

    float acc[2][8][4] = {};
    int t = threadIdx.x;
    run_mainloop(sbase, Ahp, Bhp, M - m0, Kp, Dd / 32, t, acc);

    const int lane = t & 31, w = t >> 5;
    const int g = lane >> 2, tg = lane & 3;
    const int wm = (w >> 1) * 32, wn = (w & 1) * 64;
    const float* bb = b1 + (size_t)e * Hh;

    #pragma unroll
    for (int mt = 0; mt < 2; mt++) {
        int r = wm + 16 * mt + g;
        #pragma unroll
        for (int nt = 0; nt < 8; nt++) {
            int col = n0 + wn + 8 * nt + 2 * tg;
            float* a = acc[mt][nt];
            if (m0 + r < M) {
                float v0 = gelu_f(a[0] + bb[col]);
                float v1 = gelu_f(a[1] + bb[col + 1]);
                g_h_h[((size_t)e * Bt + m0 + r) * (Hh / 2) + (col >> 1)] = packhi(v0, v1);
            }
            if (m0 + r + 8 < M) {
                float v2 = gelu_f(a[2] + bb[col]);
                float v3 = gelu_f(a[3] + bb[col + 1]);
                g_h_h[((size_t)e * Bt + m0 + r + 8) * (Hh / 2) + (col >> 1)] = packhi(v2, v3);
            }
        }
    }
}

// GEMM2 (single expert e): out[token] += gate_w * (H_e @ W2[e]^T + b2[e])
__global__ __launch_bounds__(256, 2) void k_gemm2(const float* __restrict__ b2,
                                                  float* __restrict__ out, int e) {
    int M = g_count[e];
    int m0 = blockIdx.y * 128;
    if (m0 >= M) return;
    int n0 = blockIdx.x * 128;

    extern __shared__ unsigned sm[];
    __shared__ float swg[128];
    __shared__ int stk[128];
    unsigned sbase;
    asm("{ .reg .u64 tt; cvta.to.shared.u64 tt, %1; cvt.u32.u64 %0, tt; }"
        : "=r"(sbase) : "l"(sm));

    int t = threadIdx.x;
    if (t < 128) {
        int m = m0 + t;
        if (m < M) { swg[t] = g_wgt[e * Bt + m]; stk[t] = g_tok[e * Bt + m]; }
        else       { swg[t] = 0.f; stk[t] = 0; }
    }

    const int Kp = Hh / 2;
    const unsigned* Ahp = g_h_h + ((size_t)e * Bt + m0) * Kp;
    const unsigned* Bhp = g_w2_h + (size_t)e * Dd * Kp + (size_t)n0 * Kp;

    float acc[2][8][4] = {};
    run_mainloop(sbase, Ahp, Bhp, M - m0, Kp, Hh / 32, t, acc);

    const int lane = t & 31, w = t >> 5;
    const int g = lane >> 2, tg = lane & 3;
    const int wm = (w >> 1) * 32, wn = (w & 1) * 64;
    const float* bb = b2 + (size_t)e * Dd;

    #pragma unroll
    for (int mt = 0; mt < 2; mt++) {
        int r = wm + 16 * mt + g;
        #pragma unroll
        for (int nt = 0; nt < 8; nt++) {
            int col = n0 + wn + 8 * nt + 2 * tg;
            float* a = acc[mt][nt];
            if (m0 + r < M) {
                float wg = swg[r];
                float* yo = out + (size_t)stk[r] * Dd + col;
                atomicAdd(yo,     (a[0] + bb[col])     * wg);
                atomicAdd(yo + 1, (a[1] + bb[col + 1]) * wg);
            }
            if (m0 + r + 8 < M) {
                float wg = swg[r + 8];
                float* yo = out + (size_t)stk[r + 8] * Dd + col;
                atomicAdd(yo,     (a[2] + bb[col])     * wg);
                atomicAdd(yo + 1, (a[3] + bb[col + 1]) * wg);
            }
        }
    }
}

extern "C" void kernel_launch(void* const* d_in, const int* in_sizes, int n_in,
                              void* d_out, int out_size) {
    const float* x   = (const float*)d_in[0];
    const float* gw  = (const float*)d_in[1];
    const float* gb  = (const float*)d_in[2];
    const float* lnw = (const float*)d_in[3];
    const float* lnb = (const float*)d_in[4];
    const float* w1  = (const float*)d_in[5];
    const float* b1  = (const float*)d_in[6];
    const float* w2  = (const float*)d_in[7];
    const float* b2  = (const float*)d_in[8];
    float* out = (float*)d_out;

    // one-time resource init (first call is the uncaptured correctness run)
    static cudaStream_t s_side = nullptr;
    static cudaEvent_t ev_root = nullptr, ev_side = nullptr, ev_gate = nullptr,
                       ev_done = nullptr;
    if (!s_side) {
        cudaStreamCreateWithFlags(&s_side, cudaStreamNonBlocking);
        cudaEventCreateWithFlags(&ev_root, cudaEventDisableTiming);
        cudaEventCreateWithFlags(&ev_side, cudaEventDisableTiming);
        cudaEventCreateWithFlags(&ev_gate, cudaEventDisableTiming);
        cudaEventCreateWithFlags(&ev_done, cudaEventDisableTiming);
        cudaFuncSetAttribute(k_gemm1, cudaFuncAttributeMaxDynamicSharedMemorySize, SMEM_BYTES);
        cudaFuncSetAttribute(k_gemm2, cudaFuncAttributeMaxDynamicSharedMemorySize, SMEM_BYTES);
    }

    dim3 grid1(Hh / 128, Bt / 128);
    dim3 grid2(Dd / 128, Bt / 128);

    // fork: side stream does memset + weight transposes, concurrent with gating
    cudaEventRecord(ev_root, 0);
    cudaStreamWaitEvent(s_side, ev_root, 0);
    cudaMemsetAsync(out, 0, (size_t)Bt * Dd * sizeof(float), s_side);
    k_tr_w1<<<dim3(Hh / 32, Dd / 32, Ee), 256, 0, s_side>>>(w1);
    k_tr_w2<<<dim3(Dd / 32, Hh / 32, Ee), 256, 0, s_side>>>(w2);
    cudaEventRecord(ev_side, s_side);

    k_init<<<1, 32>>>();
    k_gate<<<Bt, 256>>>(x, gw, gb, lnw, lnb, out);
    cudaEventRecord(ev_gate, 0);

    // stream 0: experts 0,1 ; side stream: experts 2,3 (expert-chunked chaining)
    cudaStreamWaitEvent(0, ev_side, 0);
    cudaStreamWaitEvent(s_side, ev_gate, 0);

    k_gemm1<<<grid1, 256, SMEM_BYTES, 0>>>(b1, out, 0, 1);
    k_gemm1<<<grid1, 256, SMEM_BYTES, s_side>>>(b1, out, 2, 0);
    k_gemm2<<<grid2, 256, SMEM_BYTES, 0>>>(b2, out, 0);
    k_gemm2<<<grid2, 256, SMEM_BYTES, s_side>>>(b2, out, 2);
    k_gemm1<<<grid1, 256, SMEM_BYTES, 0>>>(b1, out, 1, 0);
    k_gemm1<<<grid1, 256, SMEM_BYTES, s_side>>>(b1, out, 3, 0);
    k_gemm2<<<grid2, 256, SMEM_BYTES, 0>>>(b2, out, 1);
    k_gemm2<<<grid2, 256, SMEM_BYTES, s_side>>>(b2, out, 3);

    // join: main stream must observe side-stream completion
    cudaEventRecord(ev_done, s_side);
    cudaStreamWaitEvent(0, ev_done, 0);
}

// round 16
// speedup vs baseline: 1.0171x; 1.0171x over previous
#include <cuda_runtime.h>
#include <cuda_fp16.h>
#include <math.h>

#define Bt 8192
#define Dd 1024
#define Hh 4096
#define Ee 4

// output layout: y | probs | top_idx | top_w | aux
#define OFF_PROBS ((size_t)Bt * Dd)
#define OFF_IDX   (OFF_PROBS + (size_t)Bt * Ee)
#define OFF_TOPW  (OFF_IDX + (size_t)Bt * 2)
#define OFF_AUX   (OFF_TOPW + (size_t)Bt * 2)

// ---- static scratch (no allocations allowed) ----
static __device__ int      g_count[Ee];
static __device__ float    g_psum[Ee];
static __device__ int      g_tok[Ee * Bt];
static __device__ float    g_wgt[Ee * Bt];
static __device__ unsigned g_xa_h[(size_t)Ee * Bt * (Dd / 2)];
static __device__ unsigned g_h_h[(size_t)Ee * Bt * (Hh / 2)];
static __device__ unsigned g_w1_h[(size_t)Ee * Hh * (Dd / 2)];
static __device__ unsigned g_w2_h[(size_t)Ee * Dd * (Hh / 2)];

// pack two floats as fp16x2 (f0 low)
__device__ __forceinline__ unsigned packhi(float f0, float f1) {
    unsigned h;
    asm("cvt.rn.f16x2.f32 %0, %1, %2;" : "=r"(h) : "f"(f1), "f"(f0));
    return h;
}

__device__ __forceinline__ void mma_f16(float* c, const unsigned* a, const unsigned* b) {
    asm volatile(
        "mma.sync.aligned.m16n8k16.row.col.f32.f16.f16.f32 "
        "{%0,%1,%2,%3}, {%4,%5,%6,%7}, {%8,%9}, {%0,%1,%2,%3};"
        : "+f"(c[0]), "+f"(c[1]), "+f"(c[2]), "+f"(c[3])
        : "r"(a[0]), "r"(a[1]), "r"(a[2]), "r"(a[3]), "r"(b[0]), "r"(b[1]));
}

__device__ __forceinline__ void ldsm_x4(unsigned &r0, unsigned &r1, unsigned &r2,
                                        unsigned &r3, unsigned addr) {
    asm volatile("ldmatrix.sync.aligned.m8n8.x4.shared.b16 {%0,%1,%2,%3}, [%4];"
                 : "=r"(r0), "=r"(r1), "=r"(r2), "=r"(r3) : "r"(addr));
}

__device__ __forceinline__ void cpa16(unsigned dst, const unsigned* src, int predBytes) {
    asm volatile("cp.async.cg.shared.global [%0], [%1], 16, %2;\n"
                 :: "r"(dst), "l"(src), "r"(predBytes) : "memory");
}

__device__ __forceinline__ void red_add2(float* ptr, float v0, float v1) {
    asm volatile("red.global.add.v2.f32 [%0], {%1, %2};"
                 :: "l"(ptr), "f"(v0), "f"(v1) : "memory");
}

__device__ __forceinline__ float gelu_f(float v) {
    return 0.5f * v * (1.f + erff(v * 0.70710678118654752f));
}

__global__ void k_init() {
    int t = threadIdx.x;
    if (t < Ee) { g_count[t] = 0; g_psum[t] = 0.f; }
}

// transpose + pack (hi only): w [e][R][C] -> oh [e][C][R/2] (fp16x2 packed along R)
__device__ __forceinline__ void tr_body(
    const float* __restrict__ w, unsigned* __restrict__ oh, int R, int C)
{
    __shared__ float s[32][33];
    int e = blockIdx.z;
    const float* wp = w + (size_t)e * R * C;
    unsigned* ohp = oh + (size_t)e * C * (R / 2);
    int r0 = blockIdx.y * 32, c0 = blockIdx.x * 32;
    int tx = threadIdx.x & 31, ty = threadIdx.x >> 5;  // (32, 8)
    #pragma unroll
    for (int j = 0; j < 4; j++)
        s[ty + 8 * j][tx] = wp[(size_t)(r0 + ty + 8 * j) * C + c0 + tx];
    __syncthreads();
    int idx = threadIdx.x;
    int cc = idx >> 4;          // 0..15
    int rq = idx & 15;          // 0..15
    #pragma unroll
    for (int j = 0; j < 2; j++) {
        int c = cc + 16 * j;
        size_t o = (size_t)(c0 + c) * (R / 2) + (r0 >> 1) + rq;
        ohp[o] = packhi(s[2 * rq][c], s[2 * rq + 1][c]);
    }
}

__global__ __launch_bounds__(256) void k_tr_w1(const float* __restrict__ w) {
    tr_body(w, g_w1_h, Dd, Hh);
}
__global__ __launch_bounds__(256) void k_tr_w2(const float* __restrict__ w) {
    tr_body(w, g_w2_h, Hh, Dd);
}

// One block per token: LN stats, gating, softmax, top-2, outputs, packed scatter.
__global__ __launch_bounds__(256) void k_gate(
    const float* __restrict__ x, const float* __restrict__ gw,
    const float* __restrict__ gb, const float* __restrict__ lnw,
    const float* __restrict__ lnb, float* __restrict__ out)
{
    __shared__ float sx[Dd];
    __shared__ float sred[8 * 6];
    __shared__ float sfin[6];
    __shared__ float s_mu, s_rs;
    __shared__ int s_e0, s_e1, s_p0, s_p1;

    int b = blockIdx.x;
    int t = threadIdx.x;
    int lane = t & 31, wid = t >> 5;
    const float* xr = x + (size_t)b * Dd;

    #pragma unroll
    for (int d = t; d < Dd; d += 256) sx[d] = xr[d];
    __syncthreads();

    float v6[6] = {0.f, 0.f, 0.f, 0.f, 0.f, 0.f};
    #pragma unroll
    for (int d = t; d < Dd; d += 256) {
        float v = sx[d];
        v6[0] += v; v6[1] += v * v;
        v6[2] += v * gw[d];
        v6[3] += v * gw[Dd + d];
        v6[4] += v * gw[2 * Dd + d];
        v6[5] += v * gw[3 * Dd + d];
    }
    #pragma unroll
    for (int j = 0; j < 6; j++) {
        #pragma unroll
        for (int o = 16; o > 0; o >>= 1)
            v6[j] += __shfl_down_sync(0xffffffffu, v6[j], o);
    }
    if (lane == 0) {
        #pragma unroll
        for (int j = 0; j < 6; j++) sred[wid * 6 + j] = v6[j];
    }
    __syncthreads();
    if (t < 6) {
        float a = 0.f;
        #pragma unroll
        for (int w8 = 0; w8 < 8; w8++) a += sred[w8 * 6 + t];
        sfin[t] = a;
    }
    __syncthreads();

    if (t == 0) {
        float tot = sfin[0], tot2 = sfin[1];
        float lg[Ee] = { sfin[2] + gb[0], sfin[3] + gb[1],
                         sfin[4] + gb[2], sfin[5] + gb[3] };
        float mu = tot * (1.f / Dd);
        float var = tot2 * (1.f / Dd) - mu * mu;
        s_mu = mu;
        s_rs = rsqrtf(var + 1e-5f);

        float mx = lg[0];
        #pragma unroll
        for (int e = 1; e < Ee; e++) mx = fmaxf(mx, lg[e]);
        float pe[Ee], se = 0.f;
        #pragma unroll
        for (int e = 0; e < Ee; e++) { pe[e] = expf(lg[e] - mx); se += pe[e]; }
        float inv = 1.f / se;
        #pragma unroll
        for (int e = 0; e < Ee; e++) {
            pe[e] *= inv;
            out[OFF_PROBS + (size_t)b * Ee + e] = pe[e];
            atomicAdd(&g_psum[e], pe[e]);
        }
        int i0 = 0;
        #pragma unroll
        for (int e = 1; e < Ee; e++) if (pe[e] > pe[i0]) i0 = e;
        int i1 = (i0 == 0) ? 1 : 0;
        #pragma unroll
        for (int e = 0; e < Ee; e++) if (e != i0 && pe[e] > pe[i1]) i1 = e;

        float w0 = pe[i0], w1 = pe[i1];
        float sw = w0 + w1 + 1e-9f;
        w0 /= sw; w1 /= sw;

        out[OFF_IDX  + (size_t)b * 2 + 0] = (float)i0;
        out[OFF_IDX  + (size_t)b * 2 + 1] = (float)i1;
        out[OFF_TOPW + (size_t)b * 2 + 0] = w0;
        out[OFF_TOPW + (size_t)b * 2 + 1] = w1;

        int q0 = atomicAdd(&g_count[i0], 1);
        g_wgt[i0 * Bt + q0] = w0; g_tok[i0 * Bt + q0] = b;
        int q1 = atomicAdd(&g_count[i1], 1);
        g_wgt[i1 * Bt + q1] = w1; g_tok[i1 * Bt + q1] = b;
        s_e0 = i0; s_e1 = i1; s_p0 = q0; s_p1 = q1;
    }
    __syncthreads();

    float mu = s_mu, rs = s_rs;
    int e0 = s_e0, e1 = s_e1;
    unsigned* h0 = g_xa_h + ((size_t)e0 * Bt + s_p0) * (Dd / 2);
    unsigned* h1 = g_xa_h + ((size_t)e1 * Bt + s_p1) * (Dd / 2);
    const float* lw0 = lnw + (size_t)e0 * Dd; const float* lb0 = lnb + (size_t)e0 * Dd;
    const float* lw1 = lnw + (size_t)e1 * Dd; const float* lb1 = lnb + (size_t)e1 * Dd;
    for (int dq = t; dq < Dd / 2; dq += 256) {
        int d = dq * 2;
        float xn0 = (sx[d] - mu) * rs;
        float xn1 = (sx[d + 1] - mu) * rs;
        h0[dq] = packhi(xn0 * lw0[d] + lb0[d], xn1 * lw0[d + 1] + lb0[d + 1]);
        h1[dq] = packhi(xn0 * lw1[d] + lb1[d], xn1 * lw1[d + 1] + lb1[d + 1]);
    }
}

// smem layout: [stage 0/1/2][arr A,B][row 0..127][kq 0..27(pad)]
#define SOFF(s, a, r, k) ((((s) * 2 + (a)) * 128 + (r)) * 28 + (k))
#define SMEM_BYTES (3 * 2 * 128 * 28 * 4)   // 86016

// single-pass fp16 mainloop (fp32 accum): block tile 128x128, 8 warps (4m x 2n),
// warp tile 32x64. 3-stage cp.async, k32 per stage, one __syncthreads per k32.
__device__ __forceinline__ void run_mainloop(
    unsigned sbase,
    const unsigned* __restrict__ Ahp, const unsigned* __restrict__ Bhp,
    int Mrem, int Kp, int iters, int t, float acc[2][8][4])
{
    const int lane = t & 31, w = t >> 5;
    const int wm = (w >> 1) * 32, wn = (w & 1) * 64;
    const int lm = t >> 1, lc = t & 1;
    const int predA = (lm < Mrem) ? 16 : 0;
    const size_t gOfs = (size_t)lm * Kp + lc * 8;

    const int aRow = wm + (lane & 7) + ((lane >> 3) & 1) * 8;
    const int aChk = ((lane >> 4) & 1) * 4;
    const int bRow = wn + (lane & 7) + (lane >> 4) * 8;
    const int bChk = ((lane >> 3) & 1) * 4;

    #pragma unroll
    for (int p = 0; p < 2; p++) {
        size_t ko = gOfs + (size_t)p * 16;
        cpa16(sbase + SOFF(p, 0, lm, lc * 8) * 4,     Ahp + ko,     predA);
        cpa16(sbase + SOFF(p, 0, lm, lc * 8 + 4) * 4, Ahp + ko + 4, predA);
        cpa16(sbase + SOFF(p, 1, lm, lc * 8) * 4,     Bhp + ko,     16);
        cpa16(sbase + SOFF(p, 1, lm, lc * 8 + 4) * 4, Bhp + ko + 4, 16);
        asm volatile("cp.async.commit_group;\n" ::: "memory");
    }

    int s = 0, sp = 2;
    for (int it = 0; it < iters; ++it) {
        if (it + 1 < iters)
            asm volatile("cp.async.wait_group 1;\n" ::: "memory");
        else
            asm volatile("cp.async.wait_group 0;\n" ::: "memory");
        __syncthreads();

        if (it + 2 < iters) {
            size_t ko = gOfs + (size_t)(it + 2) * 16;
            cpa16(sbase + SOFF(sp, 0, lm, lc * 8) * 4,     Ahp + ko,     predA);
            cpa16(sbase + SOFF(sp, 0, lm, lc * 8 + 4) * 4, Ahp + ko + 4, predA);
            cpa16(sbase + SOFF(sp, 1, lm, lc * 8) * 4,     Bhp + ko,     16);
            cpa16(sbase + SOFF(sp, 1, lm, lc * 8 + 4) * 4, Bhp + ko + 4, 16);
            asm volatile("cp.async.commit_group;\n" ::: "memory");
        }

        #pragma unroll
        for (int kk = 0; kk < 2; kk++) {
            unsigned ah[2][4], bh[8][2];
            #pragma unroll
            for (int mt = 0; mt < 2; mt++) {
                ldsm_x4(ah[mt][0], ah[mt][1], ah[mt][2], ah[mt][3],
                        sbase + SOFF(s, 0, aRow + 16 * mt, aChk + 8 * kk) * 4);
            }
            #pragma unroll
            for (int ntp = 0; ntp < 4; ntp++) {
                ldsm_x4(bh[2 * ntp][0], bh[2 * ntp][1],
                        bh[2 * ntp + 1][0], bh[2 * ntp + 1][1],
                        sbase + SOFF(s, 1, bRow + 16 * ntp, bChk + 8 * kk) * 4);
            }
            #pragma unroll
            for (int nt = 0; nt < 8; nt++) {
                #pragma unroll
                for (int mt = 0; mt < 2; mt++) {
                    mma_f16(acc[mt][nt], ah[mt], bh[nt]);
                }
            }
        }
        s  = (s  == 2) ? 0 : s + 1;
        sp = (sp == 2) ? 0 : sp + 1;
    }
}

// GEMM1 (single expert e): H_e = GELU(Xa_e @ W1[e]^T + b1[e]); packed fp16 out.
// do_aux!=0: block (0,0) thread 0 writes the aux-loss scalar.
__global__ __launch_bounds__(256, 2) void k_gemm1(const float* __restrict__ b1,
                                                  float* __restrict__ out,
                                                  int e, int do_aux) {
    int M = g_count[e];
    int m0 = blockIdx.y * 128;

    if (do_aux && blockIdx.x == 0 && blockIdx.y == 0 && threadIdx.x == 0) {
        float a = 0.f;
        #pragma unroll
        for (int ee = 0; ee < Ee; ee++)
            a += ((float)g_count[ee] * (1.f / (Bt * 2))) * (g_psum[ee] * (1.f / Bt));
        out[OFF_AUX] = (float)Ee * a;
    }

    if (m0 >= M) return;
    int n0 = blockIdx.x * 128;

    extern __shared__ unsigned sm[];
    unsigned sbase;
    asm("{ .reg .u64 tt; cvta.to.shared.u64 tt, %1; cvt.u32.u64 %0, tt; }"
        : "=r"(sbase) : "l"(sm));

    const int Kp = Dd / 2;
    const unsigned* Ahp = g_xa_h + ((size_t)e * Bt + m0) * Kp;
    const unsigned* Bhp = g_w1_h + (size_t)e * Hh * Kp + (size_t)n0 * Kp;

    float acc[2][8][4] = {};
    int t = threadIdx.x;
    run_mainloop(sbase, Ahp, Bhp, M - m0, Kp, Dd / 32, t, acc);

    const int lane = t & 31, w = t >> 5;
    const int g = lane >> 2, tg = lane & 3;
    const int wm = (w >> 1) * 32, wn = (w & 1) * 64;
    const float* bb = b1 + (size_t)e * Hh;

    #pragma unroll
    for (int mt = 0; mt < 2; mt++) {
        int r = wm + 16 * mt + g;
        #pragma unroll
        for (int nt = 0; nt < 8; nt++) {
            int col = n0 + wn + 8 * nt + 2 * tg;
            float* a = acc[mt][nt];
            if (m0 + r < M) {
                float v0 = gelu_f(a[0] + bb[col]);
                float v1 = gelu_f(a[1] + bb[col + 1]);
                g_h_h[((size_t)e * Bt + m0 + r) * (Hh / 2) + (col >> 1)] = packhi(v0, v1);
            }
            if (m0 + r + 8 < M) {
                float v2 = gelu_f(a[2] + bb[col]);
                float v3 = gelu_f(a[3] + bb[col + 1]);
                g_h_h[((size_t)e * Bt + m0 + r + 8) * (Hh / 2) + (col >> 1)] = packhi(v2, v3);
            }
        }
    }
}

// GEMM2 (single expert e): out[token] += gate_w * (H_e @ W2[e]^T + b2[e])
// scatter-add via vectorized no-return reductions (red.global.add.v2.f32)
__global__ __launch_bounds__(256, 2) void k_gemm2(const float* __restrict__ b2,
                                                  float* __restrict__ out, int e) {
    int M = g_count[e];
    int m0 = blockIdx.y * 128;
    if (m0 >= M) return;
    int n0 = blockIdx.x * 128;

    extern __shared__ unsigned sm[];
    __shared__ float swg[128];
    __shared__ int stk[128];
    unsigned sbase;
    asm("{ .reg .u64 tt; cvta.to.shared.u64 tt, %1; cvt.u32.u64 %0, tt; }"
        : "=r"(sbase) : "l"(sm));

    int t = threadIdx.x;
    if (t < 128) {
        int m = m0 + t;
        if (m < M) { swg[t] = g_wgt[e * Bt + m]; stk[t] = g_tok[e * Bt + m]; }
        else       { swg[t] = 0.f; stk[t] = 0; }
    }

    const int Kp = Hh / 2;
    const unsigned* Ahp = g_h_h + ((size_t)e * Bt + m0) * Kp;
    const unsigned* Bhp = g_w2_h + (size_t)e * Dd * Kp + (size_t)n0 * Kp;

    float acc[2][8][4] = {};
    run_mainloop(sbase, Ahp, Bhp, M - m0, Kp, Hh / 32, t, acc);

    const int lane = t & 31, w = t >> 5;
    const int g = lane >> 2, tg = lane & 3;
    const int wm = (w >> 1) * 32, wn = (w & 1) * 64;
    const float* bb = b2 + (size_t)e * Dd;

    #pragma unroll
    for (int mt = 0; mt < 2; mt++) {
        int r = wm + 16 * mt + g;
        #pragma unroll
        for (int nt = 0; nt < 8; nt++) {
            int col = n0 + wn + 8 * nt + 2 * tg;
            float* a = acc[mt][nt];
            if (m0 + r < M) {
                float wg = swg[r];
                red_add2(out + (size_t)stk[r] * Dd + col,
                         (a[0] + bb[col]) * wg, (a[1] + bb[col + 1]) * wg);
            }
            if (m0 + r + 8 < M) {
                float wg = swg[r + 8];
                red_add2(out + (size_t)stk[r + 8] * Dd + col,
                         (a[2] + bb[col]) * wg, (a[3] + bb[col + 1]) * wg);
            }
        }
    }
}

extern "C" void kernel_launch(void* const* d_in, const int* in_sizes, int n_in,
                              void* d_out, int out_size) {
    const float* x   = (const float*)d_in[0];
    const float* gw  = (const float*)d_in[1];
    const float* gb  = (const float*)d_in[2];
    const float* lnw = (const float*)d_in[3];
    const float* lnb = (const float*)d_in[4];
    const float* w1  = (const float*)d_in[5];
    const float* b1  = (const float*)d_in[6];
    const float* w2  = (const float*)d_in[7];
    const float* b2  = (const float*)d_in[8];
    float* out = (float*)d_out;

    // one-time resource init (first call is the uncaptured correctness run)
    static cudaStream_t s_side = nullptr;
    static cudaEvent_t ev_root = nullptr, ev_side = nullptr, ev_gate = nullptr,
                       ev_done = nullptr;
    if (!s_side) {
        cudaStreamCreateWithFlags(&s_side, cudaStreamNonBlocking);
        cudaEventCreateWithFlags(&ev_root, cudaEventDisableTiming);
        cudaEventCreateWithFlags(&ev_side, cudaEventDisableTiming);
        cudaEventCreateWithFlags(&ev_gate, cudaEventDisableTiming);
        cudaEventCreateWithFlags(&ev_done, cudaEventDisableTiming);
        cudaFuncSetAttribute(k_gemm1, cudaFuncAttributeMaxDynamicSharedMemorySize, SMEM_BYTES);
        cudaFuncSetAttribute(k_gemm2, cudaFuncAttributeMaxDynamicSharedMemorySize, SMEM_BYTES);
    }

    dim3 grid1(Hh / 128, Bt / 128);
    dim3 grid2(Dd / 128, Bt / 128);

    // fork: side stream does memset + weight transposes, concurrent with gating
    cudaEventRecord(ev_root, 0);
    cudaStreamWaitEvent(s_side, ev_root, 0);
    cudaMemsetAsync(out, 0, (size_t)Bt * Dd * sizeof(float), s_side);
    k_tr_w1<<<dim3(Hh / 32, Dd / 32, Ee), 256, 0, s_side>>>(w1);
    k_tr_w2<<<dim3(Dd / 32, Hh / 32, Ee), 256, 0, s_side>>>(w2);
    cudaEventRecord(ev_side, s_side);

    k_init<<<1, 32>>>();
    k_gate<<<Bt, 256>>>(x, gw, gb, lnw, lnb, out);
    cudaEventRecord(ev_gate, 0);

    // stream 0: experts 0,1 ; side stream: experts 2,3 (expert-chunked chaining)
    cudaStreamWaitEvent(0, ev_side, 0);
    cudaStreamWaitEvent(s_side, ev_gate, 0);

    k_gemm1<<<grid1, 256, SMEM_BYTES, 0>>>(b1, out, 0, 1);
    k_gemm1<<<grid1, 256, SMEM_BYTES, s_side>>>(b1, out, 2, 0);
    k_gemm2<<<grid2, 256, SMEM_BYTES, 0>>>(b2, out, 0);
    k_gemm2<<<grid2, 256, SMEM_BYTES, s_side>>>(b2, out, 2);
    k_gemm1<<<grid1, 256, SMEM_BYTES, 0>>>(b1, out, 1, 0);
    k_gemm1<<<grid1, 256, SMEM_BYTES, s_side>>>(b1, out, 3, 0);
    k_gemm2<<<grid2, 256, SMEM_BYTES, 0>>>(b2, out, 1);
    k_gemm2<<<grid2, 256, SMEM_BYTES, s_side>>>(b2, out, 3);

    // join: main stream must observe side-stream completion
    cudaEventRecord(ev_done, s_side);
    cudaStreamWaitEvent(0, ev_done, 0);
}

// round 17
// speedup vs baseline: 1.0177x; 1.0006x over previous
#include <cuda_runtime.h>
#include <cuda_fp16.h>
#include <math.h>

#define Bt 8192
#define Dd 1024
#define Hh 4096
#define Ee 4

// output layout: y | probs | top_idx | top_w | aux
#define OFF_PROBS ((size_t)Bt * Dd)
#define OFF_IDX   (OFF_PROBS + (size_t)Bt * Ee)
#define OFF_TOPW  (OFF_IDX + (size_t)Bt * 2)
#define OFF_AUX   (OFF_TOPW + (size_t)Bt * 2)

// ---- static scratch (no allocations allowed) ----
static __device__ int      g_count[Ee];
static __device__ float    g_psum[Ee];
static __device__ int      g_tok[Ee * Bt];
static __device__ float    g_wgt[Ee * Bt];
static __device__ unsigned g_xa_h[(size_t)Ee * Bt * (Dd / 2)];
static __device__ unsigned g_h_h[(size_t)Ee * Bt * (Hh / 2)];
static __device__ unsigned g_w1_h[(size_t)Ee * Hh * (Dd / 2)];
static __device__ unsigned g_w2_h[(size_t)Ee * Dd * (Hh / 2)];

// pack two floats as fp16x2 (f0 low)
__device__ __forceinline__ unsigned packhi(float f0, float f1) {
    unsigned h;
    asm("cvt.rn.f16x2.f32 %0, %1, %2;" : "=r"(h) : "f"(f1), "f"(f0));
    return h;
}

__device__ __forceinline__ void mma_f16(float* c, const unsigned* a, const unsigned* b) {
    asm volatile(
        "mma.sync.aligned.m16n8k16.row.col.f32.f16.f16.f32 "
        "{%0,%1,%2,%3}, {%4,%5,%6,%7}, {%8,%9}, {%0,%1,%2,%3};"
        : "+f"(c[0]), "+f"(c[1]), "+f"(c[2]), "+f"(c[3])
        : "r"(a[0]), "r"(a[1]), "r"(a[2]), "r"(a[3]), "r"(b[0]), "r"(b[1]));
}

__device__ __forceinline__ void ldsm_x4(unsigned &r0, unsigned &r1, unsigned &r2,
                                        unsigned &r3, unsigned addr) {
    asm volatile("ldmatrix.sync.aligned.m8n8.x4.shared.b16 {%0,%1,%2,%3}, [%4];"
                 : "=r"(r0), "=r"(r1), "=r"(r2), "=r"(r3) : "r"(addr));
}

__device__ __forceinline__ void cpa16(unsigned dst, const unsigned* src, int predBytes) {
    asm volatile("cp.async.cg.shared.global [%0], [%1], 16, %2;\n"
                 :: "r"(dst), "l"(src), "r"(predBytes) : "memory");
}

__device__ __forceinline__ void red_add2(float* ptr, float v0, float v1) {
    asm volatile("red.global.add.v2.f32 [%0], {%1, %2};"
                 :: "l"(ptr), "f"(v0), "f"(v1) : "memory");
}

__device__ __forceinline__ float gelu_f(float v) {
    return 0.5f * v * (1.f + erff(v * 0.70710678118654752f));
}

__global__ void k_init() {
    int t = threadIdx.x;
    if (t < Ee) { g_count[t] = 0; g_psum[t] = 0.f; }
}

// transpose + pack (hi only): w [e][R][C] -> oh [e][C][R/2] (fp16x2 packed along R)
__device__ __forceinline__ void tr_body(
    const float* __restrict__ w, unsigned* __restrict__ oh, int R, int C)
{
    __shared__ float s[32][33];
    int e = blockIdx.z;
    const float* wp = w + (size_t)e * R * C;
    unsigned* ohp = oh + (size_t)e * C * (R / 2);
    int r0 = blockIdx.y * 32, c0 = blockIdx.x * 32;
    int tx = threadIdx.x & 31, ty = threadIdx.x >> 5;  // (32, 8)
    #pragma unroll
    for (int j = 0; j < 4; j++)
        s[ty + 8 * j][tx] = wp[(size_t)(r0 + ty + 8 * j) * C + c0 + tx];
    __syncthreads();
    int idx = threadIdx.x;
    int cc = idx >> 4;          // 0..15
    int rq = idx & 15;          // 0..15
    #pragma unroll
    for (int j = 0; j < 2; j++) {
        int c = cc + 16 * j;
        size_t o = (size_t)(c0 + c) * (R / 2) + (r0 >> 1) + rq;
        ohp[o] = packhi(s[2 * rq][c], s[2 * rq + 1][c]);
    }
}

__global__ __launch_bounds__(256) void k_tr_w1(const float* __restrict__ w) {
    tr_body(w, g_w1_h, Dd, Hh);
}
__global__ __launch_bounds__(256) void k_tr_w2(const float* __restrict__ w) {
    tr_body(w, g_w2_h, Hh, Dd);
}

// One block per token. Register-resident: thread t owns floats
// {2t, 2t+1, 2t+512, 2t+513} loaded once as two float2; no smem x array.
__global__ __launch_bounds__(256) void k_gate(
    const float* __restrict__ x, const float* __restrict__ gw,
    const float* __restrict__ gb, const float* __restrict__ lnw,
    const float* __restrict__ lnb, float* __restrict__ out)
{
    __shared__ float sred[8 * 6];
    __shared__ float sfin[6];
    __shared__ float s_mu, s_rs;
    __shared__ int s_e0, s_e1, s_p0, s_p1;

    int b = blockIdx.x;
    int t = threadIdx.x;
    int lane = t & 31, wid = t >> 5;
    const float* xr = x + (size_t)b * Dd;

    int d0 = 2 * t;           // first pair
    int d1 = 2 * t + 512;     // second pair
    float2 xa = *(const float2*)(xr + d0);
    float2 xb = *(const float2*)(xr + d1);

    float v6[6];
    v6[0] = xa.x + xa.y + xb.x + xb.y;
    v6[1] = xa.x * xa.x + xa.y * xa.y + xb.x * xb.x + xb.y * xb.y;
    #pragma unroll
    for (int e = 0; e < Ee; e++) {
        const float* g = gw + (size_t)e * Dd;
        float2 ga = *(const float2*)(g + d0);
        float2 gb2 = *(const float2*)(g + d1);
        v6[2 + e] = xa.x * ga.x + xa.y * ga.y + xb.x * gb2.x + xb.y * gb2.y;
    }
    #pragma unroll
    for (int j = 0; j < 6; j++) {
        #pragma unroll
        for (int o = 16; o > 0; o >>= 1)
            v6[j] += __shfl_down_sync(0xffffffffu, v6[j], o);
    }
    if (lane == 0) {
        #pragma unroll
        for (int j = 0; j < 6; j++) sred[wid * 6 + j] = v6[j];
    }
    __syncthreads();
    if (t < 6) {
        float a = 0.f;
        #pragma unroll
        for (int w8 = 0; w8 < 8; w8++) a += sred[w8 * 6 + t];
        sfin[t] = a;
    }
    __syncthreads();

    if (t == 0) {
        float tot = sfin[0], tot2 = sfin[1];
        float lg[Ee] = { sfin[2] + gb[0], sfin[3] + gb[1],
                         sfin[4] + gb[2], sfin[5] + gb[3] };
        float mu = tot * (1.f / Dd);
        float var = tot2 * (1.f / Dd) - mu * mu;
        s_mu = mu;
        s_rs = rsqrtf(var + 1e-5f);

        float mx = lg[0];
        #pragma unroll
        for (int e = 1; e < Ee; e++) mx = fmaxf(mx, lg[e]);
        float pe[Ee], se = 0.f;
        #pragma unroll
        for (int e = 0; e < Ee; e++) { pe[e] = expf(lg[e] - mx); se += pe[e]; }
        float inv = 1.f / se;
        #pragma unroll
        for (int e = 0; e < Ee; e++) {
            pe[e] *= inv;
            out[OFF_PROBS + (size_t)b * Ee + e] = pe[e];
            atomicAdd(&g_psum[e], pe[e]);
        }
        int i0 = 0;
        #pragma unroll
        for (int e = 1; e < Ee; e++) if (pe[e] > pe[i0]) i0 = e;
        int i1 = (i0 == 0) ? 1 : 0;
        #pragma unroll
        for (int e = 0; e < Ee; e++) if (e != i0 && pe[e] > pe[i1]) i1 = e;

        float w0 = pe[i0], w1 = pe[i1];
        float sw = w0 + w1 + 1e-9f;
        w0 /= sw; w1 /= sw;

        out[OFF_IDX  + (size_t)b * 2 + 0] = (float)i0;
        out[OFF_IDX  + (size_t)b * 2 + 1] = (float)i1;
        out[OFF_TOPW + (size_t)b * 2 + 0] = w0;
        out[OFF_TOPW + (size_t)b * 2 + 1] = w1;

        int q0 = atomicAdd(&g_count[i0], 1);
        g_wgt[i0 * Bt + q0] = w0; g_tok[i0 * Bt + q0] = b;
        int q1 = atomicAdd(&g_count[i1], 1);
        g_wgt[i1 * Bt + q1] = w1; g_tok[i1 * Bt + q1] = b;
        s_e0 = i0; s_e1 = i1; s_p0 = q0; s_p1 = q1;
    }
    __syncthreads();

    float mu = s_mu, rs = s_rs;
    int e0 = s_e0, e1 = s_e1;
    unsigned* h0 = g_xa_h + ((size_t)e0 * Bt + s_p0) * (Dd / 2);
    unsigned* h1 = g_xa_h + ((size_t)e1 * Bt + s_p1) * (Dd / 2);
    const float* lw0 = lnw + (size_t)e0 * Dd; const float* lb0 = lnb + (size_t)e0 * Dd;
    const float* lw1 = lnw + (size_t)e1 * Dd; const float* lb1 = lnb + (size_t)e1 * Dd;

    float na0 = (xa.x - mu) * rs, na1 = (xa.y - mu) * rs;
    float nb0 = (xb.x - mu) * rs, nb1 = (xb.y - mu) * rs;

    {
        float2 wv = *(const float2*)(lw0 + d0);
        float2 bv = *(const float2*)(lb0 + d0);
        h0[t] = packhi(na0 * wv.x + bv.x, na1 * wv.y + bv.y);
        wv = *(const float2*)(lw0 + d1);
        bv = *(const float2*)(lb0 + d1);
        h0[t + 256] = packhi(nb0 * wv.x + bv.x, nb1 * wv.y + bv.y);
    }
    {
        float2 wv = *(const float2*)(lw1 + d0);
        float2 bv = *(const float2*)(lb1 + d0);
        h1[t] = packhi(na0 * wv.x + bv.x, na1 * wv.y + bv.y);
        wv = *(const float2*)(lw1 + d1);
        bv = *(const float2*)(lb1 + d1);
        h1[t + 256] = packhi(nb0 * wv.x + bv.x, nb1 * wv.y + bv.y);
    }
}

// smem layout: [stage 0/1/2][arr A,B][row 0..127][kq 0..27(pad)]
#define SOFF(s, a, r, k) ((((s) * 2 + (a)) * 128 + (r)) * 28 + (k))
#define SMEM_BYTES (3 * 2 * 128 * 28 * 4)   // 86016

// single-pass fp16 mainloop (fp32 accum): block tile 128x128, 8 warps (4m x 2n),
// warp tile 32x64. 3-stage cp.async, k32 per stage, one __syncthreads per k32.
__device__ __forceinline__ void run_mainloop(
    unsigned sbase,
    const unsigned* __restrict__ Ahp, const unsigned* __restrict__ Bhp,
    int Mrem, int Kp, int iters, int t, float acc[2][8][4])
{
    const int lane = t & 31, w = t >> 5;
    const int wm = (w >> 1) * 32, wn = (w & 1) * 64;
    const int lm = t >> 1, lc = t & 1;
    const int predA = (lm < Mrem) ? 16 : 0;
    const size_t gOfs = (size_t)lm * Kp + lc * 8;

    const int aRow = wm + (lane & 7) + ((lane >> 3) & 1) * 8;
    const int aChk = ((lane >> 4) & 1) * 4;
    const int bRow = wn + (lane & 7) + (lane >> 4) * 8;
    const int bChk = ((lane >> 3) & 1) * 4;

    #pragma unroll
    for (int p = 0; p < 2; p++) {
        size_t ko = gOfs + (size_t)p * 16;
        cpa16(sbase + SOFF(p, 0, lm, lc * 8) * 4,     Ahp + ko,     predA);
        cpa16(sbase + SOFF(p, 0, lm, lc * 8 + 4) * 4, Ahp + ko + 4, predA);
        cpa16(sbase + SOFF(p, 1, lm, lc * 8) * 4,     Bhp + ko,     16);
        cpa16(sbase + SOFF(p, 1, lm, lc * 8 + 4) * 4, Bhp + ko + 4, 16);
        asm volatile("cp.async.commit_group;\n" ::: "memory");
    }

    int s = 0, sp = 2;
    for (int it = 0; it < iters; ++it) {
        if (it + 1 < iters)
            asm volatile("cp.async.wait_group 1;\n" ::: "memory");
        else
            asm volatile("cp.async.wait_group 0;\n" ::: "memory");
        __syncthreads();

        if (it + 2 < iters) {
            size_t ko = gOfs + (size_t)(it + 2) * 16;
            cpa16(sbase + SOFF(sp, 0, lm, lc * 8) * 4,     Ahp + ko,     predA);
            cpa16(sbase + SOFF(sp, 0, lm, lc * 8 + 4) * 4, Ahp + ko + 4, predA);
            cpa16(sbase + SOFF(sp, 1, lm, lc * 8) * 4,     Bhp + ko,     16);
            cpa16(sbase + SOFF(sp, 1, lm, lc * 8 + 4) * 4, Bhp + ko + 4, 16);
            asm volatile("cp.async.commit_group;\n" ::: "memory");
        }

        #pragma unroll
        for (int kk = 0; kk < 2; kk++) {
            unsigned ah[2][4], bh[8][2];
            #pragma unroll
            for (int mt = 0; mt < 2; mt++) {
                ldsm_x4(ah[mt][0], ah[mt][1], ah[mt][2], ah[mt][3],
                        sbase + SOFF(s, 0, aRow + 16 * mt, aChk + 8 * kk) * 4);
            }
            #pragma unroll
            for (int ntp = 0; ntp < 4; ntp++) {
                ldsm_x4(bh[2 * ntp][0], bh[2 * ntp][1],
                        bh[2 * ntp + 1][0], bh[2 * ntp + 1][1],
                        sbase + SOFF(s, 1, bRow + 16 * ntp, bChk + 8 * kk) * 4);
            }
            #pragma unroll
            for (int nt = 0; nt < 8; nt++) {
                #pragma unroll
                for (int mt = 0; mt < 2; mt++) {
                    mma_f16(acc[mt][nt], ah[mt], bh[nt]);
                }
            }
        }
        s  = (s  == 2) ? 0 : s + 1;
        sp = (sp == 2) ? 0 : sp + 1;
    }
}

// GEMM1 (single expert e): H_e = GELU(Xa_e @ W1[e]^T + b1[e]); packed fp16 out.
// do_aux!=0: block (0,0) thread 0 writes the aux-loss scalar.
__global__ __launch_bounds__(256, 2) void k_gemm1(const float* __restrict__ b1,
                                                  float* __restrict__ out,
                                                  int e, int do_aux) {
    int M = g_count[e];
    int m0 = blockIdx.y * 128;

    if (do_aux && blockIdx.x == 0 && blockIdx.y == 0 && threadIdx.x == 0) {
        float a = 0.f;
        #pragma unroll
        for (int ee = 0; ee < Ee; ee++)
            a += ((float)g_count[ee] * (1.f / (Bt * 2))) * (g_psum[ee] * (1.f / Bt));
        out[OFF_AUX] = (float)Ee * a;
    }

    if (m0 >= M) return;
    int n0 = blockIdx.x * 128;

    extern __shared__ unsigned sm[];
    unsigned sbase;
    asm("{ .reg .u64 tt; cvta.to.shared.u64 tt, %1; cvt.u32.u64 %0, tt; }"
        : "=r"(sbase) : "l"(sm));

    const int Kp = Dd / 2;
    const unsigned* Ahp = g_xa_h + ((size_t)e * Bt + m0) * Kp;
    const unsigned* Bhp = g_w1_h + (size_t)e * Hh * Kp + (size_t)n0 * Kp;

    float acc[2][8][4] = {};
    int t = threadIdx.x;
    run_mainloop(sbase, Ahp, Bhp, M - m0, Kp, Dd / 32, t, acc);

    const int lane = t & 31, w = t >> 5;
    const int g = lane >> 2, tg = lane & 3;
    const int wm = (w >> 1) * 32, wn = (w & 1) * 64;
    const float* bb = b1 + (size_t)e * Hh;

    #pragma unroll
    for (int mt = 0; mt < 2; mt++) {
        int r = wm + 16 * mt + g;
        #pragma unroll
        for (int nt = 0; nt < 8; nt++) {
            int col = n0 + wn + 8 * nt + 2 * tg;
            float* a = acc[mt][nt];
            if (m0 + r < M) {
                float v0 = gelu_f(a[0] + bb[col]);
                float v1 = gelu_f(a[1] + bb[col + 1]);
                g_h_h[((size_t)e * Bt + m0 + r) * (Hh / 2) + (col >> 1)] = packhi(v0, v1);
            }
            if (m0 + r + 8 < M) {
                float v2 = gelu_f(a[2] + bb[col]);
                float v3 = gelu_f(a[3] + bb[col + 1]);
                g_h_h[((size_t)e * Bt + m0 + r + 8) * (Hh / 2) + (col >> 1)] = packhi(v2, v3);
            }
        }
    }
}

// GEMM2 (single expert e): out[token] += gate_w * (H_e @ W2[e]^T + b2[e])
// scatter-add via vectorized no-return reductions (red.global.add.v2.f32)
__global__ __launch_bounds__(256, 2) void k_gemm2(const float* __restrict__ b2,
                                                  float* __restrict__ out, int e) {
    int M = g_count[e];
    int m0 = blockIdx.y * 128;
    if (m0 >= M) return;
    int n0 = blockIdx.x * 128;

    extern __shared__ unsigned sm[];
    __shared__ float swg[128];
    __shared__ int stk[128];
    unsigned sbase;
    asm("{ .reg .u64 tt; cvta.to.shared.u64 tt, %1; cvt.u32.u64 %0, tt; }"
        : "=r"(sbase) : "l"(sm));

    int t = threadIdx.x;
    if (t < 128) {
        int m = m0 + t;
        if (m < M) { swg[t] = g_wgt[e * Bt + m]; stk[t] = g_tok[e * Bt + m]; }
        else       { swg[t] = 0.f; stk[t] = 0; }
    }

    const int Kp = Hh / 2;
    const unsigned* Ahp = g_h_h + ((size_t)e * Bt + m0) * Kp;
    const unsigned* Bhp = g_w2_h + (size_t)e * Dd * Kp + (size_t)n0 * Kp;

    float acc[2][8][4] = {};
    run_mainloop(sbase, Ahp, Bhp, M - m0, Kp, Hh / 32, t, acc);

    const int lane = t & 31, w = t >> 5;
    const int g = lane >> 2, tg = lane & 3;
    const int wm = (w >> 1) * 32, wn = (w & 1) * 64;
    const float* bb = b2 + (size_t)e * Dd;

    #pragma unroll
    for (int mt = 0; mt < 2; mt++) {
        int r = wm + 16 * mt + g;
        #pragma unroll
        for (int nt = 0; nt < 8; nt++) {
            int col = n0 + wn + 8 * nt + 2 * tg;
            float* a = acc[mt][nt];
            if (m0 + r < M) {
                float wg = swg[r];
                red_add2(out + (size_t)stk[r] * Dd + col,
                         (a[0] + bb[col]) * wg, (a[1] + bb[col + 1]) * wg);
            }
            if (m0 + r + 8 < M) {
                float wg = swg[r + 8];
                red_add2(out + (size_t)stk[r + 8] * Dd + col,
                         (a[2] + bb[col]) * wg, (a[3] + bb[col + 1]) * wg);
            }
        }
    }
}

extern "C" void kernel_launch(void* const* d_in, const int* in_sizes, int n_in,
                              void* d_out, int out_size) {
    const float* x   = (const float*)d_in[0];
    const float* gw  = (const float*)d_in[1];
    const float* gb  = (const float*)d_in[2];
    const float* lnw = (const float*)d_in[3];
    const float* lnb = (const float*)d_in[4];
    const float* w1  = (const float*)d_in[5];
    const float* b1  = (const float*)d_in[6];
    const float* w2  = (const float*)d_in[7];
    const float* b2  = (const float*)d_in[8];
    float* out = (float*)d_out;

    // one-time resource init (first call is the uncaptured correctness run)
    static cudaStream_t s_side = nullptr;
    static cudaEvent_t ev_root = nullptr, ev_side = nullptr, ev_gate = nullptr,
                       ev_done = nullptr;
    if (!s_side) {
        cudaStreamCreateWithFlags(&s_side, cudaStreamNonBlocking);
        cudaEventCreateWithFlags(&ev_root, cudaEventDisableTiming);
        cudaEventCreateWithFlags(&ev_side, cudaEventDisableTiming);
        cudaEventCreateWithFlags(&ev_gate, cudaEventDisableTiming);
        cudaEventCreateWithFlags(&ev_done, cudaEventDisableTiming);
        cudaFuncSetAttribute(k_gemm1, cudaFuncAttributeMaxDynamicSharedMemorySize, SMEM_BYTES);
        cudaFuncSetAttribute(k_gemm2, cudaFuncAttributeMaxDynamicSharedMemorySize, SMEM_BYTES);
    }

    dim3 grid1(Hh / 128, Bt / 128);
    dim3 grid2(Dd / 128, Bt / 128);

    // fork: side stream does memset + weight transposes, concurrent with gating
    cudaEventRecord(ev_root, 0);
    cudaStreamWaitEvent(s_side, ev_root, 0);
    cudaMemsetAsync(out, 0, (size_t)Bt * Dd * sizeof(float), s_side);
    k_tr_w1<<<dim3(Hh / 32, Dd / 32, Ee), 256, 0, s_side>>>(w1);
    k_tr_w2<<<dim3(Dd / 32, Hh / 32, Ee), 256, 0, s_side>>>(w2);
    cudaEventRecord(ev_side, s_side);

    k_init<<<1, 32>>>();
    k_gate<<<Bt, 256>>>(x, gw, gb, lnw, lnb, out);
    cudaEventRecord(ev_gate, 0);

    // stream 0: experts 0,1 ; side stream: experts 2,3 (expert-chunked chaining)
    cudaStreamWaitEvent(0, ev_side, 0);
    cudaStreamWaitEvent(s_side, ev_gate, 0);

    k_gemm1<<<grid1, 256, SMEM_BYTES, 0>>>(b1, out, 0, 1);
    k_gemm1<<<grid1, 256, SMEM_BYTES, s_side>>>(b1, out, 2, 0);
    k_gemm2<<<grid2, 256, SMEM_BYTES, 0>>>(b2, out, 0);
    k_gemm2<<<grid2, 256, SMEM_BYTES, s_side>>>(b2, out, 2);
    k_gemm1<<<grid1, 256, SMEM_BYTES, 0>>>(b1, out, 1, 0);
    k_gemm1<<<grid1, 256, SMEM_BYTES, s_side>>>(b1, out, 3, 0);
    k_gemm2<<<grid2, 256, SMEM_BYTES, 0>>>(b2, out, 1);
    k_gemm2<<<grid2, 256, SMEM_BYTES, s_side>>>(b2, out, 3);

    // join: main stream must observe side-stream completion
    cudaEventRecord(ev_done, s_side);
    cudaStreamWaitEvent(0, ev_done, 0);
}